// round 11
// baseline (speedup 1.0000x reference)
#include <cuda_runtime.h>
#include <math.h>

// Problem constants
#define NT   1100            // 100 support + 1000 query
#define NTP  1152            // NT padded to multiple of 128 (GEMM tiles)
#define DM   640             // d_model
#define NSUP 100
#define SP   100             // 10*10 spatial
#define TK   10              // top-k
#define RB   256             // reduction blocks (fixed for determinism)
#define BMW  40              // bitmap words per row (ceil(1100/32)=35, padded)
#define NW   35              // bitmap words actually used

// ---------------- scratch (device globals; no allocation allowed) ----------
__device__ float    g_x [NTP * DM];              // spatial means (padded rows = 0)
__device__ float    g_q [NTP * DM];              // emb_q (padded rows = 0 via GEMM)
__device__ float    g_v [NTP * DM];              // emb_v
__device__ float    g_sq[NT];                    // ||emb_q_i||^2
__device__ float    g_w [(size_t)NT * NT];       // distances, then exp-kernel (in place)
__device__ int      g_tk[NT * TK];               // topk indices per row
__device__ unsigned g_bm[NT * BMW];              // symmetric adjacency bitmap
__device__ float    g_dsi[NT];                   // D^{-1/2}
__device__ double   g_ps[RB];                    // partial sums
__device__ double   g_pq[RB];                    // partial sums of squares
__device__ float    g_invstd;

// ---------------- 1) spatial mean: x[n,c] = mean_s emb[n,c,s] --------------
// one warp per (n,c); 100 floats = 25 float4, lanes 0..24
__global__ void mean_kernel(const float* __restrict__ sup,
                            const float* __restrict__ qry) {
    int gw   = (blockIdx.x * blockDim.x + threadIdx.x) >> 5;
    int lane = threadIdx.x & 31;
    if (gw >= NT * DM) return;
    int n = gw / DM, c = gw - n * DM;
    const float* p = (n < NSUP)
        ? (sup + (size_t)n * DM * SP + (size_t)c * SP)
        : (qry + (size_t)(n - NSUP) * DM * SP + (size_t)c * SP);
    float s = 0.f;
    if (lane < 25) {
        float4 v = ((const float4*)p)[lane];
        s = (v.x + v.y) + (v.z + v.w);
    }
#pragma unroll
    for (int o = 16; o > 0; o >>= 1) s += __shfl_down_sync(0xffffffffu, s, o);
    if (lane == 0) g_x[gw] = s * (1.0f / SP);
}

// ---------------- big fp32 GEMM: 128x64 tile, 8x4 micro, double-buffered ---
// C[M,N] = A[M,K] @ B[N,K]^T. All loads unguarded: caller guarantees
// A has >= gridDim.y*128 rows, B has >= gridDim.x*64 rows, K % 8 == 0.
// Writes guarded by (Mreal, Nreal). blockIdx.z picks (B0,C0) vs (B1,C1).
// EPI: C[r,c] = (r==c) ? 0 : max(sq_r + sq_c - 2*acc, 0)
template<bool EPI>
__global__ void __launch_bounds__(256)
gemm_big(const float* __restrict__ A,
         const float* __restrict__ B0, const float* __restrict__ B1,
         float* __restrict__ C0, float* __restrict__ C1,
         int K, int ldc, int Mreal, int Nreal) {
    const float* __restrict__ B = blockIdx.z ? B1 : B0;
    float* __restrict__ C = blockIdx.z ? C1 : C0;

    __shared__ float As[2][8][132];   // k-major, conflict-free pitch
    __shared__ float Bs[2][8][68];

    int row0 = blockIdx.y * 128, col0 = blockIdx.x * 64;
    int tid = threadIdx.x;            // 256 threads
    int tx = tid & 15, ty = tid >> 4; // 16x16 -> micro 8(rows) x 4(cols)
    int arow = tid >> 1,          ah = tid & 1;   // A: 128 rows x 2 half-k
    int brow = (tid & 127) >> 1,  bh = tid & 1;   // B: 64 rows x 2 half-k (tid<128)

    const float4* Ap = (const float4*)(A + (size_t)(row0 + arow) * K + ah * 4);
    const float4* Bp = (const float4*)(B + (size_t)(col0 + brow) * K + bh * 4);

    float acc[8][4] = {};
    int nk = K >> 3;

    float4 av = Ap[0];
    float4 bv = make_float4(0.f, 0.f, 0.f, 0.f);
    if (tid < 128) bv = Bp[0];

    int buf = 0;
    // store tile 0
    As[buf][ah * 4 + 0][arow] = av.x;
    As[buf][ah * 4 + 1][arow] = av.y;
    As[buf][ah * 4 + 2][arow] = av.z;
    As[buf][ah * 4 + 3][arow] = av.w;
    if (tid < 128) {
        Bs[buf][bh * 4 + 0][brow] = bv.x;
        Bs[buf][bh * 4 + 1][brow] = bv.y;
        Bs[buf][bh * 4 + 2][brow] = bv.z;
        Bs[buf][bh * 4 + 3][brow] = bv.w;
    }
    __syncthreads();

    for (int kt = 1; kt < nk; kt++) {
        // prefetch next tile (global), overlapped with compute below
        av = Ap[kt * 2];
        if (tid < 128) bv = Bp[kt * 2];

        const float (*as)[132] = As[buf];
        const float (*bs)[68]  = Bs[buf];
#pragma unroll
        for (int k = 0; k < 8; k++) {
            float4 a0 = *(const float4*)&as[k][ty * 8];
            float4 a1 = *(const float4*)&as[k][ty * 8 + 4];
            float4 b4 = *(const float4*)&bs[k][tx * 4];
            float a[8] = {a0.x, a0.y, a0.z, a0.w, a1.x, a1.y, a1.z, a1.w};
            float b[4] = {b4.x, b4.y, b4.z, b4.w};
#pragma unroll
            for (int i = 0; i < 8; i++)
#pragma unroll
                for (int j = 0; j < 4; j++) acc[i][j] += a[i] * b[j];
        }
        // store prefetched tile into the other buffer
        int nb = buf ^ 1;
        As[nb][ah * 4 + 0][arow] = av.x;
        As[nb][ah * 4 + 1][arow] = av.y;
        As[nb][ah * 4 + 2][arow] = av.z;
        As[nb][ah * 4 + 3][arow] = av.w;
        if (tid < 128) {
            Bs[nb][bh * 4 + 0][brow] = bv.x;
            Bs[nb][bh * 4 + 1][brow] = bv.y;
            Bs[nb][bh * 4 + 2][brow] = bv.z;
            Bs[nb][bh * 4 + 3][brow] = bv.w;
        }
        __syncthreads();
        buf = nb;
    }
    {   // last tile
        const float (*as)[132] = As[buf];
        const float (*bs)[68]  = Bs[buf];
#pragma unroll
        for (int k = 0; k < 8; k++) {
            float4 a0 = *(const float4*)&as[k][ty * 8];
            float4 a1 = *(const float4*)&as[k][ty * 8 + 4];
            float4 b4 = *(const float4*)&bs[k][tx * 4];
            float a[8] = {a0.x, a0.y, a0.z, a0.w, a1.x, a1.y, a1.z, a1.w};
            float b[4] = {b4.x, b4.y, b4.z, b4.w};
#pragma unroll
            for (int i = 0; i < 8; i++)
#pragma unroll
                for (int j = 0; j < 4; j++) acc[i][j] += a[i] * b[j];
        }
    }

#pragma unroll
    for (int i = 0; i < 8; i++) {
        int r = row0 + ty * 8 + i;
        if (r >= Mreal) continue;
        float sqr = EPI ? g_sq[r] : 0.f;
#pragma unroll
        for (int j = 0; j < 4; j++) {
            int c = col0 + tx * 4 + j;
            if (c >= Nreal) continue;
            float val;
            if (EPI) {
                val = (r == c) ? 0.f
                               : fmaxf(sqr + g_sq[c] - 2.0f * acc[i][j], 0.f);
            } else {
                val = acc[i][j];
            }
            C[(size_t)r * ldc + c] = val;
        }
    }
}

// ---------------- sq[i] = ||emb_q_i||^2, one warp per row ------------------
__global__ void sq_kernel() {
    int gw   = (blockIdx.x * blockDim.x + threadIdx.x) >> 5;
    int lane = threadIdx.x & 31;
    if (gw >= NT) return;
    const float4* r = (const float4*)(g_q + (size_t)gw * DM);  // 160 float4
    float s = 0.f;
    for (int k = lane; k < DM / 4; k += 32) {
        float4 v = r[k];
        s += v.x * v.x + v.y * v.y + v.z * v.z + v.w * v.w;
    }
#pragma unroll
    for (int o = 16; o > 0; o >>= 1) s += __shfl_down_sync(0xffffffffu, s, o);
    if (lane == 0) g_sq[gw] = s;
}

// ---------------- deterministic two-stage sum / sumsq reduction ------------
__global__ void reduce_partial_kernel() {
    double s = 0.0, q = 0.0;
    for (size_t idx = (size_t)blockIdx.x * blockDim.x + threadIdx.x;
         idx < (size_t)NT * NT; idx += (size_t)gridDim.x * blockDim.x) {
        double v = (double)g_w[idx];
        s += v; q += v * v;
    }
    __shared__ double ss[256], qq[256];
    ss[threadIdx.x] = s; qq[threadIdx.x] = q; __syncthreads();
    for (int st = 128; st > 0; st >>= 1) {
        if (threadIdx.x < st) {
            ss[threadIdx.x] += ss[threadIdx.x + st];
            qq[threadIdx.x] += qq[threadIdx.x + st];
        }
        __syncthreads();
    }
    if (threadIdx.x == 0) { g_ps[blockIdx.x] = ss[0]; g_pq[blockIdx.x] = qq[0]; }
}

__global__ void reduce_final_kernel() {
    __shared__ double ss[RB], qq[RB];
    ss[threadIdx.x] = g_ps[threadIdx.x];
    qq[threadIdx.x] = g_pq[threadIdx.x];
    __syncthreads();
    for (int st = RB / 2; st > 0; st >>= 1) {
        if (threadIdx.x < st) {
            ss[threadIdx.x] += ss[threadIdx.x + st];
            qq[threadIdx.x] += qq[threadIdx.x + st];
        }
        __syncthreads();
    }
    if (threadIdx.x == 0) {
        // diag entries are exactly 0 => sums over all == sums over off-diag
        double cnt = (double)NT * NT - NT;
        double sum = ss[0], sumsq = qq[0];
        double var = (sumsq - sum * sum / cnt) / (cnt - 1.0);   // unbiased
        g_invstd = (float)(1.0 / sqrt(var));
    }
}

// ---------------- fused transform + per-row top-10 (warp per row) ----------
// w := exp(-0.5 * w * invstd)  (diag 0 -> 1), then iterative argmax,
// ties broken to lowest index (matches jax.lax.top_k).
// __expf is monotone, so the selected top-k SET is unchanged vs expf.
__global__ void topk_kernel() {
    int gw   = (blockIdx.x * blockDim.x + threadIdx.x) >> 5;
    int lane = threadIdx.x & 31;
    if (gw >= NT) return;
    float is = g_invstd;
    float* row = g_w + (size_t)gw * NT;
    float vals[NW];
#pragma unroll
    for (int s = 0; s < NW; s++) {
        int j = lane + 32 * s;
        float e = -2.f;
        if (j < NT) { e = __expf(-0.5f * row[j] * is); row[j] = e; }
        vals[s] = e;
    }
    for (int t = 0; t < TK; t++) {
        float best = -3.f; int bslot = 0;
#pragma unroll
        for (int s = 0; s < NW; s++) {        // strict > keeps lowest j in-lane
            if (vals[s] > best) { best = vals[s]; bslot = s; }
        }
        int bj = lane + 32 * bslot;
#pragma unroll
        for (int o = 16; o > 0; o >>= 1) {
            float ov = __shfl_down_sync(0xffffffffu, best, o);
            int   oj = __shfl_down_sync(0xffffffffu, bj,   o);
            if (ov > best || (ov == best && oj < bj)) { best = ov; bj = oj; }
        }
        bj = __shfl_sync(0xffffffffu, bj, 0);
        if (lane == 0) g_tk[gw * TK + t] = bj;
        if ((bj & 31) == lane) vals[bj >> 5] = -2.f;   // exclude (values in (0,1])
    }
}

// ---------------- symmetric adjacency bitmap from top-k lists --------------
__global__ void edge_kernel() {
    int idx = blockIdx.x * blockDim.x + threadIdx.x;
    if (idx >= NT * TK) return;
    int i = idx / TK;
    int j = g_tk[idx];
    atomicOr(&g_bm[i * BMW + (j >> 5)], 1u << (j & 31));
    atomicOr(&g_bm[j * BMW + (i >> 5)], 1u << (i & 31));
}

// ---------------- degree (row sums over mask; w is bitwise symmetric) ------
__global__ void deg_kernel() {
    int gw   = (blockIdx.x * blockDim.x + threadIdx.x) >> 5;
    int lane = threadIdx.x & 31;
    if (gw >= NT) return;
    float s = 0.f;
    for (int wi = lane; wi < NW; wi += 32) {
        unsigned m = g_bm[gw * BMW + wi];
        while (m) {
            int b = __ffs(m) - 1; m &= m - 1;
            s += g_w[(size_t)gw * NT + wi * 32 + b];
        }
    }
#pragma unroll
    for (int o = 16; o > 0; o >>= 1) s += __shfl_down_sync(0xffffffffu, s, o);
    if (lane == 0) g_dsi[gw] = sqrtf(1.0f / (s + 2.2204460492503131e-16f));
}

// ---------------- sparse out[i,:] = dsi_i * sum_j w_ij*dsi_j * v[j,:] ------
// block per row; neighbor list built serially (ALL 35 words), ascending order
__global__ void spout_kernel(float* __restrict__ out) {
    int i = blockIdx.x;
    __shared__ int   nbr[1120];
    __shared__ float coef[1120];
    __shared__ int   s_cnt;
    int tid = threadIdx.x;
    if (tid == 0) {
        int off = 0;
        for (int wi = 0; wi < NW; wi++) {            // cover all 1100 columns
            unsigned m = g_bm[i * BMW + wi];
            while (m) {
                int b = __ffs(m) - 1; m &= m - 1;
                nbr[off++] = wi * 32 + b;
            }
        }
        s_cnt = off;
    }
    __syncthreads();
    int cnt = s_cnt;
    for (int t = tid; t < cnt; t += blockDim.x) {
        int j = nbr[t];
        coef[t] = g_w[(size_t)i * NT + j] * g_dsi[j];
    }
    __syncthreads();
    float di = g_dsi[i];
    for (int c = tid; c < DM; c += blockDim.x) {
        float acc = 0.f;
        for (int t = 0; t < cnt; t++)
            acc += coef[t] * g_v[(size_t)nbr[t] * DM + c];
        out[(size_t)i * DM + c] = di * acc;
    }
}

// ---------------- host launcher --------------------------------------------
extern "C" void kernel_launch(void* const* d_in, const int* in_sizes, int n_in,
                              void* d_out, int out_size) {
    const float* sup = (const float*)d_in[0];   // [100,640,10,10]
    const float* qry = (const float*)d_in[2];   // [1000,640,10,10]
    const float* Wq  = (const float*)d_in[4];   // [640,640]
    const float* Wv  = (const float*)d_in[5];   // [640,640]
    float* out = (float*)d_out;                 // [1100,640]

    float *px, *pq, *pv;
    void* pbm;
    cudaGetSymbolAddress((void**)&px, g_x);
    cudaGetSymbolAddress((void**)&pq, g_q);
    cudaGetSymbolAddress((void**)&pv, g_v);
    float* pw;
    cudaGetSymbolAddress((void**)&pw, g_w);
    cudaGetSymbolAddress(&pbm, g_bm);

    // zero the padding rows of g_x so GEMM loads are safe and produce
    // zero padding rows in g_q / g_v (which in turn feed zeros to the Gram)
    cudaMemsetAsync(px + (size_t)NT * DM, 0, (size_t)(NTP - NT) * DM * sizeof(float));

    // 1) spatial mean
    mean_kernel<<<(NT * DM * 32 + 255) / 256, 256>>>(sup, qry);

    // 2) emb_q / emb_v = x @ W^T  (one fused launch, blockIdx.z selects W)
    {
        dim3 grid(DM / 64, NTP / 128, 2);
        gemm_big<false><<<grid, 256>>>(px, Wq, Wv, pq, pv,
                                       DM, DM, NTP, DM);
    }

    // 3) sq norms, then Gram with fused distance epilogue (w in place)
    int wr_blocks = (NT * 32 + 255) / 256;      // warp-per-row grids
    sq_kernel<<<wr_blocks, 256>>>();
    {
        dim3 grid(NTP / 64, NTP / 128, 1);
        gemm_big<true><<<grid, 256>>>(pq, pq, pq, pw, pw,
                                      DM, NT, NT, NT);
    }

    // 4) std normalization (deterministic two-stage reduction)
    reduce_partial_kernel<<<RB, 256>>>();
    reduce_final_kernel<<<1, RB>>>();

    // 5) fused exp transform + top-k
    topk_kernel<<<wr_blocks, 256>>>();

    // 6) symmetric mask bitmap + degrees
    cudaMemsetAsync(pbm, 0, sizeof(unsigned) * NT * BMW);
    edge_kernel<<<(NT * TK + 255) / 256, 256>>>();
    deg_kernel<<<wr_blocks, 256>>>();

    // 7) sparse S @ emb_v with Laplacian scaling folded in
    spout_kernel<<<NT, 256>>>(out);
}

// round 12
// speedup vs baseline: 1.0089x; 1.0089x over previous
#include <cuda_runtime.h>
#include <math.h>

// Problem constants
#define NT   1100            // 100 support + 1000 query
#define NTP  1152            // NT padded to multiple of 128 (GEMM tiles)
#define DM   640             // d_model
#define NSUP 100
#define SP   100             // 10*10 spatial
#define TK   10              // top-k
#define RB   256             // reduction blocks (fixed for determinism)
#define BMW  40              // bitmap words per row (ceil(1100/32)=35, padded)
#define NW   35              // bitmap words actually used

// ---------------- scratch (device globals; no allocation allowed) ----------
__device__ float    g_x [NTP * DM];              // spatial means (padded rows = 0)
__device__ float    g_q [NTP * DM];              // emb_q (padded rows = 0 via GEMM)
__device__ float    g_v [NTP * DM];              // emb_v
__device__ float    g_sq[NT];                    // ||emb_q_i||^2
__device__ float    g_w [(size_t)NT * NT];       // distances, then exp-kernel (in place)
__device__ int      g_tk[NT * TK];               // topk indices per row
__device__ unsigned g_bm[NT * BMW];              // symmetric adjacency bitmap
__device__ float    g_dsi[NT];                   // D^{-1/2}
__device__ double   g_ps[RB];                    // partial sums
__device__ double   g_pq[RB];                    // partial sums of squares
__device__ float    g_invstd;

// ---------------- 1) spatial mean: x[n,c] = mean_s emb[n,c,s] --------------
// one warp per (n,c); 100 floats = 25 float4, lanes 0..24
__global__ void mean_kernel(const float* __restrict__ sup,
                            const float* __restrict__ qry) {
    int gw   = (blockIdx.x * blockDim.x + threadIdx.x) >> 5;
    int lane = threadIdx.x & 31;
    if (gw >= NT * DM) return;
    int n = gw / DM, c = gw - n * DM;
    const float* p = (n < NSUP)
        ? (sup + (size_t)n * DM * SP + (size_t)c * SP)
        : (qry + (size_t)(n - NSUP) * DM * SP + (size_t)c * SP);
    float s = 0.f;
    if (lane < 25) {
        float4 v = ((const float4*)p)[lane];
        s = (v.x + v.y) + (v.z + v.w);
    }
#pragma unroll
    for (int o = 16; o > 0; o >>= 1) s += __shfl_down_sync(0xffffffffu, s, o);
    if (lane == 0) g_x[gw] = s * (1.0f / SP);
}

// ---------------- big fp32 GEMM: 128x64 tile, 8x4 micro, double-buffered ---
// C[M,N] = A[M,K] @ B[N,K]^T. All loads unguarded: caller guarantees
// A has >= gridDim.y*128 rows, B has >= gridDim.x*64 rows, K % 8 == 0.
// Writes guarded by (Mreal, Nreal). blockIdx.z picks (B0,C0) vs (B1,C1).
// EPI: C[r,c] = (r==c) ? 0 : max(sq_r + sq_c - 2*acc, 0)
template<bool EPI>
__global__ void __launch_bounds__(256)
gemm_big(const float* __restrict__ A,
         const float* __restrict__ B0, const float* __restrict__ B1,
         float* __restrict__ C0, float* __restrict__ C1,
         int K, int ldc, int Mreal, int Nreal) {
    const float* __restrict__ B = blockIdx.z ? B1 : B0;
    float* __restrict__ C = blockIdx.z ? C1 : C0;

    __shared__ float As[2][8][132];   // k-major, conflict-free pitch
    __shared__ float Bs[2][8][68];

    int row0 = blockIdx.y * 128, col0 = blockIdx.x * 64;
    int tid = threadIdx.x;            // 256 threads
    int tx = tid & 15, ty = tid >> 4; // 16x16 -> micro 8(rows) x 4(cols)
    int arow = tid >> 1,          ah = tid & 1;   // A: 128 rows x 2 half-k
    int brow = (tid & 127) >> 1,  bh = tid & 1;   // B: 64 rows x 2 half-k (tid<128)

    const float4* Ap = (const float4*)(A + (size_t)(row0 + arow) * K + ah * 4);
    const float4* Bp = (const float4*)(B + (size_t)(col0 + brow) * K + bh * 4);

    float acc[8][4] = {};
    int nk = K >> 3;

    float4 av = Ap[0];
    float4 bv = make_float4(0.f, 0.f, 0.f, 0.f);
    if (tid < 128) bv = Bp[0];

    int buf = 0;
    // store tile 0
    As[buf][ah * 4 + 0][arow] = av.x;
    As[buf][ah * 4 + 1][arow] = av.y;
    As[buf][ah * 4 + 2][arow] = av.z;
    As[buf][ah * 4 + 3][arow] = av.w;
    if (tid < 128) {
        Bs[buf][bh * 4 + 0][brow] = bv.x;
        Bs[buf][bh * 4 + 1][brow] = bv.y;
        Bs[buf][bh * 4 + 2][brow] = bv.z;
        Bs[buf][bh * 4 + 3][brow] = bv.w;
    }
    __syncthreads();

    for (int kt = 1; kt < nk; kt++) {
        // prefetch next tile (global), overlapped with compute below
        av = Ap[kt * 2];
        if (tid < 128) bv = Bp[kt * 2];

        const float (*as)[132] = As[buf];
        const float (*bs)[68]  = Bs[buf];
#pragma unroll
        for (int k = 0; k < 8; k++) {
            float4 a0 = *(const float4*)&as[k][ty * 8];
            float4 a1 = *(const float4*)&as[k][ty * 8 + 4];
            float4 b4 = *(const float4*)&bs[k][tx * 4];
            float a[8] = {a0.x, a0.y, a0.z, a0.w, a1.x, a1.y, a1.z, a1.w};
            float b[4] = {b4.x, b4.y, b4.z, b4.w};
#pragma unroll
            for (int i = 0; i < 8; i++)
#pragma unroll
                for (int j = 0; j < 4; j++) acc[i][j] += a[i] * b[j];
        }
        // store prefetched tile into the other buffer
        int nb = buf ^ 1;
        As[nb][ah * 4 + 0][arow] = av.x;
        As[nb][ah * 4 + 1][arow] = av.y;
        As[nb][ah * 4 + 2][arow] = av.z;
        As[nb][ah * 4 + 3][arow] = av.w;
        if (tid < 128) {
            Bs[nb][bh * 4 + 0][brow] = bv.x;
            Bs[nb][bh * 4 + 1][brow] = bv.y;
            Bs[nb][bh * 4 + 2][brow] = bv.z;
            Bs[nb][bh * 4 + 3][brow] = bv.w;
        }
        __syncthreads();
        buf = nb;
    }
    {   // last tile
        const float (*as)[132] = As[buf];
        const float (*bs)[68]  = Bs[buf];
#pragma unroll
        for (int k = 0; k < 8; k++) {
            float4 a0 = *(const float4*)&as[k][ty * 8];
            float4 a1 = *(const float4*)&as[k][ty * 8 + 4];
            float4 b4 = *(const float4*)&bs[k][tx * 4];
            float a[8] = {a0.x, a0.y, a0.z, a0.w, a1.x, a1.y, a1.z, a1.w};
            float b[4] = {b4.x, b4.y, b4.z, b4.w};
#pragma unroll
            for (int i = 0; i < 8; i++)
#pragma unroll
                for (int j = 0; j < 4; j++) acc[i][j] += a[i] * b[j];
        }
    }

#pragma unroll
    for (int i = 0; i < 8; i++) {
        int r = row0 + ty * 8 + i;
        if (r >= Mreal) continue;
        float sqr = EPI ? g_sq[r] : 0.f;
#pragma unroll
        for (int j = 0; j < 4; j++) {
            int c = col0 + tx * 4 + j;
            if (c >= Nreal) continue;
            float val;
            if (EPI) {
                val = (r == c) ? 0.f
                               : fmaxf(sqr + g_sq[c] - 2.0f * acc[i][j], 0.f);
            } else {
                val = acc[i][j];
            }
            C[(size_t)r * ldc + c] = val;
        }
    }
}

// ---------------- sq[i] = ||emb_q_i||^2, one warp per row ------------------
__global__ void sq_kernel() {
    int gw   = (blockIdx.x * blockDim.x + threadIdx.x) >> 5;
    int lane = threadIdx.x & 31;
    if (gw >= NT) return;
    const float4* r = (const float4*)(g_q + (size_t)gw * DM);  // 160 float4
    float s = 0.f;
    for (int k = lane; k < DM / 4; k += 32) {
        float4 v = r[k];
        s += v.x * v.x + v.y * v.y + v.z * v.z + v.w * v.w;
    }
#pragma unroll
    for (int o = 16; o > 0; o >>= 1) s += __shfl_down_sync(0xffffffffu, s, o);
    if (lane == 0) g_sq[gw] = s;
}

// ---------------- deterministic two-stage sum / sumsq reduction ------------
__global__ void reduce_partial_kernel() {
    double s = 0.0, q = 0.0;
    for (size_t idx = (size_t)blockIdx.x * blockDim.x + threadIdx.x;
         idx < (size_t)NT * NT; idx += (size_t)gridDim.x * blockDim.x) {
        double v = (double)g_w[idx];
        s += v; q += v * v;
    }
    __shared__ double ss[256], qq[256];
    ss[threadIdx.x] = s; qq[threadIdx.x] = q; __syncthreads();
    for (int st = 128; st > 0; st >>= 1) {
        if (threadIdx.x < st) {
            ss[threadIdx.x] += ss[threadIdx.x + st];
            qq[threadIdx.x] += qq[threadIdx.x + st];
        }
        __syncthreads();
    }
    if (threadIdx.x == 0) { g_ps[blockIdx.x] = ss[0]; g_pq[blockIdx.x] = qq[0]; }
}

__global__ void reduce_final_kernel() {
    __shared__ double ss[RB], qq[RB];
    ss[threadIdx.x] = g_ps[threadIdx.x];
    qq[threadIdx.x] = g_pq[threadIdx.x];
    __syncthreads();
    for (int st = RB / 2; st > 0; st >>= 1) {
        if (threadIdx.x < st) {
            ss[threadIdx.x] += ss[threadIdx.x + st];
            qq[threadIdx.x] += qq[threadIdx.x + st];
        }
        __syncthreads();
    }
    if (threadIdx.x == 0) {
        // diag entries are exactly 0 => sums over all == sums over off-diag
        double cnt = (double)NT * NT - NT;
        double sum = ss[0], sumsq = qq[0];
        double var = (sumsq - sum * sum / cnt) / (cnt - 1.0);   // unbiased
        g_invstd = (float)(1.0 / sqrt(var));
    }
}

// ---------------- fused transform + per-row top-10 (warp per row) ----------
// w := exp(-0.5 * w * invstd)  (diag 0 -> 1), then iterative argmax,
// ties broken to lowest index (matches jax.lax.top_k).
// __expf is monotone, so the selected top-k SET is unchanged vs expf.
__global__ void topk_kernel() {
    int gw   = (blockIdx.x * blockDim.x + threadIdx.x) >> 5;
    int lane = threadIdx.x & 31;
    if (gw >= NT) return;
    float is = g_invstd;
    float* row = g_w + (size_t)gw * NT;
    float vals[NW];
#pragma unroll
    for (int s = 0; s < NW; s++) {
        int j = lane + 32 * s;
        float e = -2.f;
        if (j < NT) { e = __expf(-0.5f * row[j] * is); row[j] = e; }
        vals[s] = e;
    }
    for (int t = 0; t < TK; t++) {
        float best = -3.f; int bslot = 0;
#pragma unroll
        for (int s = 0; s < NW; s++) {        // strict > keeps lowest j in-lane
            if (vals[s] > best) { best = vals[s]; bslot = s; }
        }
        int bj = lane + 32 * bslot;
#pragma unroll
        for (int o = 16; o > 0; o >>= 1) {
            float ov = __shfl_down_sync(0xffffffffu, best, o);
            int   oj = __shfl_down_sync(0xffffffffu, bj,   o);
            if (ov > best || (ov == best && oj < bj)) { best = ov; bj = oj; }
        }
        bj = __shfl_sync(0xffffffffu, bj, 0);
        if (lane == 0) g_tk[gw * TK + t] = bj;
        if ((bj & 31) == lane) vals[bj >> 5] = -2.f;   // exclude (values in (0,1])
    }
}

// ---------------- symmetric adjacency bitmap from top-k lists --------------
__global__ void edge_kernel() {
    int idx = blockIdx.x * blockDim.x + threadIdx.x;
    if (idx >= NT * TK) return;
    int i = idx / TK;
    int j = g_tk[idx];
    atomicOr(&g_bm[i * BMW + (j >> 5)], 1u << (j & 31));
    atomicOr(&g_bm[j * BMW + (i >> 5)], 1u << (i & 31));
}

// ---------------- degree (row sums over mask; w is bitwise symmetric) ------
__global__ void deg_kernel() {
    int gw   = (blockIdx.x * blockDim.x + threadIdx.x) >> 5;
    int lane = threadIdx.x & 31;
    if (gw >= NT) return;
    float s = 0.f;
    for (int wi = lane; wi < NW; wi += 32) {
        unsigned m = g_bm[gw * BMW + wi];
        while (m) {
            int b = __ffs(m) - 1; m &= m - 1;
            s += g_w[(size_t)gw * NT + wi * 32 + b];
        }
    }
#pragma unroll
    for (int o = 16; o > 0; o >>= 1) s += __shfl_down_sync(0xffffffffu, s, o);
    if (lane == 0) g_dsi[gw] = sqrtf(1.0f / (s + 2.2204460492503131e-16f));
}

// ---------------- sparse out[i,:] = dsi_i * sum_j w_ij*dsi_j * v[j,:] ------
// block per row; neighbor list built serially (ALL 35 words), ascending order
__global__ void spout_kernel(float* __restrict__ out) {
    int i = blockIdx.x;
    __shared__ int   nbr[1120];
    __shared__ float coef[1120];
    __shared__ int   s_cnt;
    int tid = threadIdx.x;
    if (tid == 0) {
        int off = 0;
        for (int wi = 0; wi < NW; wi++) {            // cover all 1100 columns
            unsigned m = g_bm[i * BMW + wi];
            while (m) {
                int b = __ffs(m) - 1; m &= m - 1;
                nbr[off++] = wi * 32 + b;
            }
        }
        s_cnt = off;
    }
    __syncthreads();
    int cnt = s_cnt;
    for (int t = tid; t < cnt; t += blockDim.x) {
        int j = nbr[t];
        coef[t] = g_w[(size_t)i * NT + j] * g_dsi[j];
    }
    __syncthreads();
    float di = g_dsi[i];
    for (int c = tid; c < DM; c += blockDim.x) {
        float acc = 0.f;
        for (int t = 0; t < cnt; t++)
            acc += coef[t] * g_v[(size_t)nbr[t] * DM + c];
        out[(size_t)i * DM + c] = di * acc;
    }
}

// ---------------- host launcher --------------------------------------------
extern "C" void kernel_launch(void* const* d_in, const int* in_sizes, int n_in,
                              void* d_out, int out_size) {
    const float* sup = (const float*)d_in[0];   // [100,640,10,10]
    const float* qry = (const float*)d_in[2];   // [1000,640,10,10]
    const float* Wq  = (const float*)d_in[4];   // [640,640]
    const float* Wv  = (const float*)d_in[5];   // [640,640]
    float* out = (float*)d_out;                 // [1100,640]

    float *px, *pq, *pv;
    void* pbm;
    cudaGetSymbolAddress((void**)&px, g_x);
    cudaGetSymbolAddress((void**)&pq, g_q);
    cudaGetSymbolAddress((void**)&pv, g_v);
    float* pw;
    cudaGetSymbolAddress((void**)&pw, g_w);
    cudaGetSymbolAddress(&pbm, g_bm);

    // zero the padding rows of g_x so GEMM loads are safe and produce
    // zero padding rows in g_q / g_v (which in turn feed zeros to the Gram)
    cudaMemsetAsync(px + (size_t)NT * DM, 0, (size_t)(NTP - NT) * DM * sizeof(float));

    // 1) spatial mean
    mean_kernel<<<(NT * DM * 32 + 255) / 256, 256>>>(sup, qry);

    // 2) emb_q / emb_v = x @ W^T  (one fused launch, blockIdx.z selects W)
    {
        dim3 grid(DM / 64, NTP / 128, 2);
        gemm_big<false><<<grid, 256>>>(px, Wq, Wv, pq, pv,
                                       DM, DM, NTP, DM);
    }

    // 3) sq norms, then Gram with fused distance epilogue (w in place)
    int wr_blocks = (NT * 32 + 255) / 256;      // warp-per-row grids
    sq_kernel<<<wr_blocks, 256>>>();
    {
        dim3 grid(NTP / 64, NTP / 128, 1);
        gemm_big<true><<<grid, 256>>>(pq, pq, pq, pw, pw,
                                      DM, NT, NT, NT);
    }

    // 4) std normalization (deterministic two-stage reduction)
    reduce_partial_kernel<<<RB, 256>>>();
    reduce_final_kernel<<<1, RB>>>();

    // 5) fused exp transform + top-k
    topk_kernel<<<wr_blocks, 256>>>();

    // 6) symmetric mask bitmap + degrees
    cudaMemsetAsync(pbm, 0, sizeof(unsigned) * NT * BMW);
    edge_kernel<<<(NT * TK + 255) / 256, 256>>>();
    deg_kernel<<<wr_blocks, 256>>>();

    // 7) sparse S @ emb_v with Laplacian scaling folded in
    spout_kernel<<<NT, 256>>>(out);
}

// round 13
// speedup vs baseline: 1.1190x; 1.1092x over previous
#include <cuda_runtime.h>
#include <math.h>

// Problem constants
#define NT   1100            // 100 support + 1000 query
#define NTP  1152            // NT padded to multiple of 128 (GEMM tiles)
#define DM   640             // d_model
#define NSUP 100
#define SP   100             // 10*10 spatial
#define TK   10              // top-k
#define RB   256             // reduction blocks (fixed for determinism)
#define BMW  40              // bitmap words per row (ceil(1100/32)=35, padded)
#define NW   35              // bitmap words actually used

// ---------------- scratch (device globals; no allocation allowed) ----------
__device__ float    g_x  [NTP * DM];             // spatial means (padded rows = 0)
__device__ float    g_q  [NTP * DM];             // emb_q
__device__ float    g_v  [NTP * DM];             // emb_v
__device__ float    g_qp0[NTP * DM];             // K-split partials
__device__ float    g_qp1[NTP * DM];
__device__ float    g_vp0[NTP * DM];
__device__ float    g_vp1[NTP * DM];
__device__ float    g_gp0[(size_t)NTP * NTP];    // gram K-split partials
__device__ float    g_gp1[(size_t)NTP * NTP];
__device__ float    g_sq [NT];                   // ||emb_q_i||^2
__device__ float    g_w  [(size_t)NT * NT];      // distances, then exp-kernel
__device__ int      g_tk [NT * TK];              // topk indices per row
__device__ unsigned g_bm [NT * BMW];             // symmetric adjacency bitmap
__device__ float    g_dsi[NT];                   // D^{-1/2}
__device__ double   g_ps [RB];                   // partial sums
__device__ double   g_pq [RB];                   // partial sums of squares
__device__ float    g_invstd;

// ---------------- 1) spatial mean: x[n,c] = mean_s emb[n,c,s] --------------
__global__ void mean_kernel(const float* __restrict__ sup,
                            const float* __restrict__ qry) {
    int gw   = (blockIdx.x * blockDim.x + threadIdx.x) >> 5;
    int lane = threadIdx.x & 31;
    if (gw >= NT * DM) return;
    int n = gw / DM, c = gw - n * DM;
    const float* p = (n < NSUP)
        ? (sup + (size_t)n * DM * SP + (size_t)c * SP)
        : (qry + (size_t)(n - NSUP) * DM * SP + (size_t)c * SP);
    float s = 0.f;
    if (lane < 25) {
        float4 v = ((const float4*)p)[lane];
        s = (v.x + v.y) + (v.z + v.w);
    }
#pragma unroll
    for (int o = 16; o > 0; o >>= 1) s += __shfl_down_sync(0xffffffffu, s, o);
    if (lane == 0) g_x[gw] = s * (1.0f / SP);
}

// ---------------- K-split fp32 GEMM: 128x64 tile, 8x4 micro, dbl-buffered --
// Partial C = A[:,koff:koff+K/2] @ B[:,koff:koff+K/2]^T  (both K-major rows).
// All loads AND stores unguarded: A rows >= gridDim.y*128, B rows >=
// gridDim.x*64, C is a full padded partial buffer with pitch ldc.
// gridDim.z == 4: z = (wsel | ksel<<1), B = wsel?B1:B0, C = Cz.
// gridDim.z == 2: z = ksel, B = B0, C = (z?C1:C0).
__global__ void __launch_bounds__(256)
gemm_ksplit(const float* __restrict__ A,
            const float* __restrict__ B0, const float* __restrict__ B1,
            float* __restrict__ C0, float* __restrict__ C1,
            float* __restrict__ C2, float* __restrict__ C3,
            int Kfull, int ldc) {
    int z = blockIdx.z;
    int wsel, ksel;
    if (gridDim.z == 4) { wsel = z & 1; ksel = z >> 1; }
    else                { wsel = 0;     ksel = z;      }
    const float* __restrict__ B = wsel ? B1 : B0;
    float* __restrict__ C = (z == 0) ? C0 : (z == 1) ? C1 : (z == 2) ? C2 : C3;
    int Khalf = Kfull >> 1;
    int koff  = ksel * Khalf;

    __shared__ float As[2][8][132];   // k-major, conflict-free pitch
    __shared__ float Bs[2][8][68];

    int row0 = blockIdx.y * 128, col0 = blockIdx.x * 64;
    int tid = threadIdx.x;            // 256 threads
    int tx = tid & 15, ty = tid >> 4; // micro 8(rows) x 4(cols)
    int arow = tid >> 1,          ah = tid & 1;   // A: 128 rows x 2 half-k
    int brow = (tid & 127) >> 1,  bh = tid & 1;   // B: 64 rows x 2 half-k

    const float4* Ap = (const float4*)(A + (size_t)(row0 + arow) * Kfull + koff + ah * 4);
    const float4* Bp = (const float4*)(B + (size_t)(col0 + brow) * Kfull + koff + bh * 4);

    float acc[8][4] = {};
    int nk = Khalf >> 3;
    // Kfull/8 float4 per row advance per 8-k tile => stride in float4 = Kfull/4? No:
    // Ap indexes float4 within the row; +8 floats per tile = +2 float4.

    float4 av = Ap[0];
    float4 bv = make_float4(0.f, 0.f, 0.f, 0.f);
    if (tid < 128) bv = Bp[0];

    int buf = 0;
    As[buf][ah * 4 + 0][arow] = av.x;
    As[buf][ah * 4 + 1][arow] = av.y;
    As[buf][ah * 4 + 2][arow] = av.z;
    As[buf][ah * 4 + 3][arow] = av.w;
    if (tid < 128) {
        Bs[buf][bh * 4 + 0][brow] = bv.x;
        Bs[buf][bh * 4 + 1][brow] = bv.y;
        Bs[buf][bh * 4 + 2][brow] = bv.z;
        Bs[buf][bh * 4 + 3][brow] = bv.w;
    }
    __syncthreads();

    for (int kt = 1; kt < nk; kt++) {
        av = Ap[kt * 2];
        if (tid < 128) bv = Bp[kt * 2];

        const float (*as)[132] = As[buf];
        const float (*bs)[68]  = Bs[buf];
#pragma unroll
        for (int k = 0; k < 8; k++) {
            float4 a0 = *(const float4*)&as[k][ty * 8];
            float4 a1 = *(const float4*)&as[k][ty * 8 + 4];
            float4 b4 = *(const float4*)&bs[k][tx * 4];
            float a[8] = {a0.x, a0.y, a0.z, a0.w, a1.x, a1.y, a1.z, a1.w};
            float b[4] = {b4.x, b4.y, b4.z, b4.w};
#pragma unroll
            for (int i = 0; i < 8; i++)
#pragma unroll
                for (int j = 0; j < 4; j++) acc[i][j] += a[i] * b[j];
        }
        int nb = buf ^ 1;
        As[nb][ah * 4 + 0][arow] = av.x;
        As[nb][ah * 4 + 1][arow] = av.y;
        As[nb][ah * 4 + 2][arow] = av.z;
        As[nb][ah * 4 + 3][arow] = av.w;
        if (tid < 128) {
            Bs[nb][bh * 4 + 0][brow] = bv.x;
            Bs[nb][bh * 4 + 1][brow] = bv.y;
            Bs[nb][bh * 4 + 2][brow] = bv.z;
            Bs[nb][bh * 4 + 3][brow] = bv.w;
        }
        __syncthreads();
        buf = nb;
    }
    {   // last tile
        const float (*as)[132] = As[buf];
        const float (*bs)[68]  = Bs[buf];
#pragma unroll
        for (int k = 0; k < 8; k++) {
            float4 a0 = *(const float4*)&as[k][ty * 8];
            float4 a1 = *(const float4*)&as[k][ty * 8 + 4];
            float4 b4 = *(const float4*)&bs[k][tx * 4];
            float a[8] = {a0.x, a0.y, a0.z, a0.w, a1.x, a1.y, a1.z, a1.w};
            float b[4] = {b4.x, b4.y, b4.z, b4.w};
#pragma unroll
            for (int i = 0; i < 8; i++)
#pragma unroll
                for (int j = 0; j < 4; j++) acc[i][j] += a[i] * b[j];
        }
    }

    // unguarded vectorized store of the partial tile
#pragma unroll
    for (int i = 0; i < 8; i++) {
        int r = row0 + ty * 8 + i;
        float4 o = make_float4(acc[i][0], acc[i][1], acc[i][2], acc[i][3]);
        *(float4*)(C + (size_t)r * ldc + col0 + tx * 4) = o;
    }
}

// ---------------- combine qv partials + fused ||q||^2 ----------------------
// one block per padded row; 160 threads = DM/4 float4 lanes
__global__ void __launch_bounds__(160) combine_qv_kernel() {
    int r = blockIdx.x;                 // 0..NTP-1
    int t = threadIdx.x;                // 0..159
    size_t base = (size_t)r * DM;
    float4 q0 = ((const float4*)(g_qp0 + base))[t];
    float4 q1 = ((const float4*)(g_qp1 + base))[t];
    float4 q  = make_float4(q0.x + q1.x, q0.y + q1.y, q0.z + q1.z, q0.w + q1.w);
    ((float4*)(g_q + base))[t] = q;
    float4 v0 = ((const float4*)(g_vp0 + base))[t];
    float4 v1 = ((const float4*)(g_vp1 + base))[t];
    ((float4*)(g_v + base))[t] =
        make_float4(v0.x + v1.x, v0.y + v1.y, v0.z + v1.z, v0.w + v1.w);

    // block-reduce sum of q^2 (5 warps)
    float s = q.x * q.x + q.y * q.y + q.z * q.z + q.w * q.w;
#pragma unroll
    for (int o = 16; o > 0; o >>= 1) s += __shfl_down_sync(0xffffffffu, s, o);
    __shared__ float ws[5];
    if ((t & 31) == 0) ws[t >> 5] = s;
    __syncthreads();
    if (t == 0 && r < NT)
        g_sq[r] = (ws[0] + ws[1]) + (ws[2] + ws[3]) + ws[4];
}

// ---------------- combine gram partials -> distances + fused sum/sumsq -----
// row-strided over blocks (no integer division); writes w (NT x NT)
__global__ void __launch_bounds__(256) combine_gram_kernel() {
    int tid = threadIdx.x;
    double s = 0.0, q = 0.0;
    for (int i = blockIdx.x; i < NT; i += gridDim.x) {
        float sqi = g_sq[i];
        const float* p0 = g_gp0 + (size_t)i * NTP;
        const float* p1 = g_gp1 + (size_t)i * NTP;
        float* wrow = g_w + (size_t)i * NT;
        for (int j = tid; j < NT; j += 256) {
            float p = p0[j] + p1[j];
            float d = (i == j) ? 0.f : fmaxf(sqi + g_sq[j] - 2.0f * p, 0.f);
            wrow[j] = d;
            double dv = (double)d;
            s += dv; q += dv * dv;
        }
    }
    __shared__ double ss[256], qq[256];
    ss[tid] = s; qq[tid] = q; __syncthreads();
    for (int st = 128; st > 0; st >>= 1) {
        if (tid < st) { ss[tid] += ss[tid + st]; qq[tid] += qq[tid + st]; }
        __syncthreads();
    }
    if (tid == 0) { g_ps[blockIdx.x] = ss[0]; g_pq[blockIdx.x] = qq[0]; }
}

__global__ void reduce_final_kernel() {
    __shared__ double ss[RB], qq[RB];
    ss[threadIdx.x] = g_ps[threadIdx.x];
    qq[threadIdx.x] = g_pq[threadIdx.x];
    __syncthreads();
    for (int st = RB / 2; st > 0; st >>= 1) {
        if (threadIdx.x < st) {
            ss[threadIdx.x] += ss[threadIdx.x + st];
            qq[threadIdx.x] += qq[threadIdx.x + st];
        }
        __syncthreads();
    }
    if (threadIdx.x == 0) {
        // diag entries are exactly 0 => sums over all == sums over off-diag
        double cnt = (double)NT * NT - NT;
        double sum = ss[0], sumsq = qq[0];
        double var = (sumsq - sum * sum / cnt) / (cnt - 1.0);   // unbiased
        g_invstd = (float)(1.0 / sqrt(var));
    }
}

// ---------------- fused transform + per-row top-10 (warp per row) ----------
// w := exp(-0.5 * w * invstd)  (diag 0 -> 1), then iterative argmax,
// ties broken to lowest index (matches jax.lax.top_k).
__global__ void topk_kernel() {
    int gw   = (blockIdx.x * blockDim.x + threadIdx.x) >> 5;
    int lane = threadIdx.x & 31;
    if (gw >= NT) return;
    float is = g_invstd;
    float* row = g_w + (size_t)gw * NT;
    float vals[NW];
#pragma unroll
    for (int s = 0; s < NW; s++) {
        int j = lane + 32 * s;
        float e = -2.f;
        if (j < NT) { e = __expf(-0.5f * row[j] * is); row[j] = e; }
        vals[s] = e;
    }
    for (int t = 0; t < TK; t++) {
        float best = -3.f; int bslot = 0;
#pragma unroll
        for (int s = 0; s < NW; s++) {        // strict > keeps lowest j in-lane
            if (vals[s] > best) { best = vals[s]; bslot = s; }
        }
        int bj = lane + 32 * bslot;
#pragma unroll
        for (int o = 16; o > 0; o >>= 1) {
            float ov = __shfl_down_sync(0xffffffffu, best, o);
            int   oj = __shfl_down_sync(0xffffffffu, bj,   o);
            if (ov > best || (ov == best && oj < bj)) { best = ov; bj = oj; }
        }
        bj = __shfl_sync(0xffffffffu, bj, 0);
        if (lane == 0) g_tk[gw * TK + t] = bj;
        if ((bj & 31) == lane) vals[bj >> 5] = -2.f;   // exclude (values in (0,1])
    }
}

// ---------------- symmetric adjacency bitmap from top-k lists --------------
__global__ void edge_kernel() {
    int idx = blockIdx.x * blockDim.x + threadIdx.x;
    if (idx >= NT * TK) return;
    int i = idx / TK;
    int j = g_tk[idx];
    atomicOr(&g_bm[i * BMW + (j >> 5)], 1u << (j & 31));
    atomicOr(&g_bm[j * BMW + (i >> 5)], 1u << (i & 31));
}

// ---------------- degree (row sums over mask; w is bitwise symmetric) ------
__global__ void deg_kernel() {
    int gw   = (blockIdx.x * blockDim.x + threadIdx.x) >> 5;
    int lane = threadIdx.x & 31;
    if (gw >= NT) return;
    float s = 0.f;
    for (int wi = lane; wi < NW; wi += 32) {
        unsigned m = g_bm[gw * BMW + wi];
        while (m) {
            int b = __ffs(m) - 1; m &= m - 1;
            s += g_w[(size_t)gw * NT + wi * 32 + b];
        }
    }
#pragma unroll
    for (int o = 16; o > 0; o >>= 1) s += __shfl_down_sync(0xffffffffu, s, o);
    if (lane == 0) g_dsi[gw] = sqrtf(1.0f / (s + 2.2204460492503131e-16f));
}

// ---------------- sparse out[i,:] = dsi_i * sum_j w_ij*dsi_j * v[j,:] ------
__global__ void spout_kernel(float* __restrict__ out) {
    int i = blockIdx.x;
    __shared__ int   nbr[1120];
    __shared__ float coef[1120];
    __shared__ int   s_cnt;
    int tid = threadIdx.x;
    if (tid == 0) {
        int off = 0;
        for (int wi = 0; wi < NW; wi++) {            // cover all 1100 columns
            unsigned m = g_bm[i * BMW + wi];
            while (m) {
                int b = __ffs(m) - 1; m &= m - 1;
                nbr[off++] = wi * 32 + b;
            }
        }
        s_cnt = off;
    }
    __syncthreads();
    int cnt = s_cnt;
    for (int t = tid; t < cnt; t += blockDim.x) {
        int j = nbr[t];
        coef[t] = g_w[(size_t)i * NT + j] * g_dsi[j];
    }
    __syncthreads();
    float di = g_dsi[i];
    for (int c = tid; c < DM; c += blockDim.x) {
        float acc = 0.f;
        for (int t = 0; t < cnt; t++)
            acc += coef[t] * g_v[(size_t)nbr[t] * DM + c];
        out[(size_t)i * DM + c] = di * acc;
    }
}

// ---------------- host launcher --------------------------------------------
extern "C" void kernel_launch(void* const* d_in, const int* in_sizes, int n_in,
                              void* d_out, int out_size) {
    const float* sup = (const float*)d_in[0];   // [100,640,10,10]
    const float* qry = (const float*)d_in[2];   // [1000,640,10,10]
    const float* Wq  = (const float*)d_in[4];   // [640,640]
    const float* Wv  = (const float*)d_in[5];   // [640,640]
    float* out = (float*)d_out;                 // [1100,640]

    float *px, *pq, *pqp0, *pqp1, *pvp0, *pvp1, *pgp0, *pgp1;
    void* pbm;
    cudaGetSymbolAddress((void**)&px,  g_x);
    cudaGetSymbolAddress((void**)&pq,  g_q);
    cudaGetSymbolAddress((void**)&pqp0, g_qp0);
    cudaGetSymbolAddress((void**)&pqp1, g_qp1);
    cudaGetSymbolAddress((void**)&pvp0, g_vp0);
    cudaGetSymbolAddress((void**)&pvp1, g_vp1);
    cudaGetSymbolAddress((void**)&pgp0, g_gp0);
    cudaGetSymbolAddress((void**)&pgp1, g_gp1);
    cudaGetSymbolAddress(&pbm, g_bm);

    // zero the padding rows of g_x (pad rows propagate as zeros through GEMMs)
    cudaMemsetAsync(px + (size_t)NT * DM, 0, (size_t)(NTP - NT) * DM * sizeof(float));

    // 1) spatial mean
    mean_kernel<<<(NT * DM * 32 + 255) / 256, 256>>>(sup, qry);

    // 2) emb_q / emb_v = x @ W^T, K-split=2 fused over both weights (z=4)
    {
        dim3 grid(DM / 64, NTP / 128, 4);
        gemm_ksplit<<<grid, 256>>>(px, Wq, Wv, pqp0, pvp0, pqp1, pvp1, DM, DM);
    }
    // combine partials + fused sq norms
    combine_qv_kernel<<<NTP, 160>>>();

    // 3) Gram = emb_q @ emb_q^T, K-split=2
    {
        dim3 grid(NTP / 64, NTP / 128, 2);
        gemm_ksplit<<<grid, 256>>>(pq, pq, pq, pgp0, pgp1, pgp0, pgp1, DM, NTP);
    }
    // combine + distance epilogue + fused variance partials
    combine_gram_kernel<<<RB, 256>>>();
    reduce_final_kernel<<<1, RB>>>();

    // 4) fused exp transform + top-k
    int wr_blocks = (NT * 32 + 255) / 256;
    topk_kernel<<<wr_blocks, 256>>>();

    // 5) symmetric mask bitmap + degrees
    cudaMemsetAsync(pbm, 0, sizeof(unsigned) * NT * BMW);
    edge_kernel<<<(NT * TK + 255) / 256, 256>>>();
    deg_kernel<<<wr_blocks, 256>>>();

    // 6) sparse S @ emb_v with Laplacian scaling folded in
    spout_kernel<<<NT, 256>>>(out);
}